// round 3
// baseline (speedup 1.0000x reference)
#include <cuda_runtime.h>
#include <cuda_bf16.h>
#include <cstdint>

// ---------------------------------------------------------------------------
// GCN 2-layer: h = relu(GCNConv(x,W1,b1)); z = GCNConv(h,W2,b2)
// out = [ segment_max(z,batch) (64x7) ; log_softmax(z) (Nx7) ]
// NOTE: edge_index/batch are int32 (JAX x64 disabled downcasts int64->int32).
// ---------------------------------------------------------------------------

#define MAXN 100352
#define NUM_GRAPHS 64
#define HID 16
#define NCLS 7

// Scratch (device globals: allocation-free rule)
__device__ int      g_deg[MAXN];
__device__ float    g_dinv[MAXN];
__device__ float4   g_h0[MAXN * 4];   // [N][16]  x@W1
__device__ float4   g_a1[MAXN * 4];   // [N][16]  aggregated + b1 (pre-relu)
__device__ float4   g_h1[MAXN * 2];   // [N][8]   relu(a1)@W2 (7 used, 1 pad)
__device__ float4   g_z [MAXN * 2];   // [N][8]   aggregated z (7 used, 1 pad)
__device__ unsigned g_gkey[NUM_GRAPHS * NCLS];

// ---- helpers --------------------------------------------------------------

__device__ __forceinline__ void redAdd4(float* p, float a, float b, float c, float d) {
    asm volatile(
        "{ .reg .u64 pg; cvta.to.global.u64 pg, %0;\n\t"
        "  red.global.add.v4.f32 [pg], {%1, %2, %3, %4}; }"
        :: "l"(p), "f"(a), "f"(b), "f"(c), "f"(d) : "memory");
}

// monotone order-preserving float->uint key
__device__ __forceinline__ unsigned fkey(float f) {
    unsigned u = __float_as_uint(f);
    return (u & 0x80000000u) ? ~u : (u | 0x80000000u);
}
__device__ __forceinline__ float funkey(unsigned u) {
    return __uint_as_float((u & 0x80000000u) ? (u ^ 0x80000000u) : ~u);
}

// ---- pipeline kernels -----------------------------------------------------

__global__ void init_kernel(int N) {
    int i = blockIdx.x * blockDim.x + threadIdx.x;
    if (i < N) g_deg[i] = 1;                       // self-loop
    if (i < NUM_GRAPHS * NCLS) g_gkey[i] = 0u;
}

__global__ void deg_kernel(const int* __restrict__ ei, int E) {
    int e = blockIdx.x * blockDim.x + threadIdx.x;
    if (e >= E) return;
    int d = ei[E + e];
    atomicAdd(&g_deg[d], 1);
}

__global__ void dinv_kernel(int N) {
    int i = blockIdx.x * blockDim.x + threadIdx.x;
    if (i < N) g_dinv[i] = rsqrtf((float)g_deg[i]);
}

// GEMM1: h0[N,16] = x[N,F] @ W1[F,16]; also a1 = h0*dinv^2 + b1 (fused epi).
// Block: 512 nodes, 256 threads. Thread: 4 nodes (strided by 128) x 8 cols.
__global__ __launch_bounds__(256) void gemm1_kernel(
    const float* __restrict__ x, const float* __restrict__ W1,
    const float* __restrict__ b1, int N, int F)
{
    __shared__ float xs[512 * 17];   // [node][k], stride 17 (conflict-free)
    __shared__ float ws[16 * 16];    // [kk][c]

    const int t  = threadIdx.x;
    const int n0 = blockIdx.x * 512;
    const int cg = t & 1;            // col half: 8 cols
    const int g  = t >> 1;           // node group 0..127

    float acc[4][8];
#pragma unroll
    for (int j = 0; j < 4; j++)
#pragma unroll
        for (int c = 0; c < 8; c++) acc[j][c] = 0.f;

    for (int k0 = 0; k0 < F; k0 += 16) {
        {   // ws: 256 floats by 256 threads
            int kk = t >> 4, c = t & 15;
            ws[kk * 16 + c] = (k0 + kk < F) ? W1[(size_t)(k0 + kk) * 16 + c] : 0.f;
        }
        // xs: 512*16 floats, coalesced (warp covers 2 node-rows x 16 k)
#pragma unroll
        for (int i = 0; i < 32; i++) {
            int idx = t + 256 * i;
            int row = idx >> 4, kl = idx & 15;
            int node = n0 + row, k = k0 + kl;
            float v = 0.f;
            if (node < N && k < F) v = x[(size_t)node * F + k];
            xs[row * 17 + kl] = v;
        }
        __syncthreads();
#pragma unroll
        for (int kk = 0; kk < 16; kk++) {
            float4 w0 = *(const float4*)&ws[kk * 16 + cg * 8];
            float4 w1 = *(const float4*)&ws[kk * 16 + cg * 8 + 4];
#pragma unroll
            for (int j = 0; j < 4; j++) {
                float xv = xs[(g + 128 * j) * 17 + kk];
                acc[j][0] += xv * w0.x; acc[j][1] += xv * w0.y;
                acc[j][2] += xv * w0.z; acc[j][3] += xv * w0.w;
                acc[j][4] += xv * w1.x; acc[j][5] += xv * w1.y;
                acc[j][6] += xv * w1.z; acc[j][7] += xv * w1.w;
            }
        }
        __syncthreads();
    }
#pragma unroll
    for (int j = 0; j < 4; j++) {
        int node = n0 + g + 128 * j;
        if (node < N) {
            float di = g_dinv[node];
            float c2 = di * di;
            float* hp = (float*)g_h0 + (size_t)node * 16 + cg * 8;
            float* ap = (float*)g_a1 + (size_t)node * 16 + cg * 8;
            *(float4*)hp       = make_float4(acc[j][0], acc[j][1], acc[j][2], acc[j][3]);
            *(float4*)(hp + 4) = make_float4(acc[j][4], acc[j][5], acc[j][6], acc[j][7]);
            *(float4*)ap       = make_float4(acc[j][0] * c2 + __ldg(&b1[cg * 8 + 0]),
                                             acc[j][1] * c2 + __ldg(&b1[cg * 8 + 1]),
                                             acc[j][2] * c2 + __ldg(&b1[cg * 8 + 2]),
                                             acc[j][3] * c2 + __ldg(&b1[cg * 8 + 3]));
            *(float4*)(ap + 4) = make_float4(acc[j][4] * c2 + __ldg(&b1[cg * 8 + 4]),
                                             acc[j][5] * c2 + __ldg(&b1[cg * 8 + 5]),
                                             acc[j][6] * c2 + __ldg(&b1[cg * 8 + 6]),
                                             acc[j][7] * c2 + __ldg(&b1[cg * 8 + 7]));
        }
    }
}

__global__ void agg1_kernel(const int* __restrict__ ei, int E) {
    int e = blockIdx.x * blockDim.x + threadIdx.x;
    if (e >= E) return;
    int s = ei[e];
    int d = ei[E + e];
    float coef = g_dinv[s] * g_dinv[d];
    const float4* hp = g_h0 + (size_t)s * 4;
    float* ap = (float*)(g_a1 + (size_t)d * 4);
#pragma unroll
    for (int q = 0; q < 4; q++) {
        float4 v = hp[q];
        redAdd4(ap + q * 4, v.x * coef, v.y * coef, v.z * coef, v.w * coef);
    }
}

// h1[N,8] = relu(a1) @ W2[16,7]  (col 7 = 0 pad); also z = h1*dinv^2 + b2 (fused).
__global__ void gemm2_kernel(const float* __restrict__ W2,
                             const float* __restrict__ b2, int N) {
    __shared__ float w2s[HID * NCLS];
    int t = threadIdx.x;
    if (t < HID * NCLS) w2s[t] = W2[t];
    __syncthreads();
    int n = blockIdx.x * blockDim.x + t;
    if (n >= N) return;
    const float4* ap = g_a1 + (size_t)n * 4;
    float r[16];
#pragma unroll
    for (int q = 0; q < 4; q++) {
        float4 v = ap[q];
        r[q * 4 + 0] = fmaxf(v.x, 0.f); r[q * 4 + 1] = fmaxf(v.y, 0.f);
        r[q * 4 + 2] = fmaxf(v.z, 0.f); r[q * 4 + 3] = fmaxf(v.w, 0.f);
    }
    float o[NCLS];
#pragma unroll
    for (int c = 0; c < NCLS; c++) o[c] = 0.f;
#pragma unroll
    for (int j = 0; j < 16; j++) {
        float rv = r[j];
#pragma unroll
        for (int c = 0; c < NCLS; c++) o[c] += rv * w2s[j * NCLS + c];
    }
    float* hp = (float*)(g_h1 + (size_t)n * 2);
    *(float4*)hp       = make_float4(o[0], o[1], o[2], o[3]);
    *(float4*)(hp + 4) = make_float4(o[4], o[5], o[6], 0.f);

    float di = g_dinv[n];
    float c2 = di * di;
    float* zp = (float*)(g_z + (size_t)n * 2);
    *(float4*)zp       = make_float4(o[0] * c2 + __ldg(&b2[0]), o[1] * c2 + __ldg(&b2[1]),
                                     o[2] * c2 + __ldg(&b2[2]), o[3] * c2 + __ldg(&b2[3]));
    *(float4*)(zp + 4) = make_float4(o[4] * c2 + __ldg(&b2[4]), o[5] * c2 + __ldg(&b2[5]),
                                     o[6] * c2 + __ldg(&b2[6]), 0.f);
}

__global__ void agg2_kernel(const int* __restrict__ ei, int E) {
    int e = blockIdx.x * blockDim.x + threadIdx.x;
    if (e >= E) return;
    int s = ei[e];
    int d = ei[E + e];
    float coef = g_dinv[s] * g_dinv[d];
    const float* hp = (const float*)(g_h1 + (size_t)s * 2);
    float* zp = (float*)(g_z + (size_t)d * 2);
    float4 v0 = *(const float4*)hp;
    float4 v1 = *(const float4*)(hp + 4);
    redAdd4(zp,     v0.x * coef, v0.y * coef, v0.z * coef, v0.w * coef);
    redAdd4(zp + 4, v1.x * coef, v1.y * coef, v1.z * coef, 0.f);  // pad slot += 0
}

// segment_max (via ordered-uint atomicMax) + log_softmax, fused
__global__ void segmax_logsm_kernel(const int* __restrict__ batch,
                                    float* __restrict__ out, int N) {
    int n = blockIdx.x * blockDim.x + threadIdx.x;
    if (n >= N) return;
    const float* zp = (const float*)(g_z + (size_t)n * 2);
    float4 z0 = *(const float4*)zp;
    float4 z1 = *(const float4*)(zp + 4);
    float zz[NCLS] = { z0.x, z0.y, z0.z, z0.w, z1.x, z1.y, z1.z };

    int b = batch[n];
#pragma unroll
    for (int c = 0; c < NCLS; c++)
        atomicMax(&g_gkey[b * NCLS + c], fkey(zz[c]));

    float m = zz[0];
#pragma unroll
    for (int c = 1; c < NCLS; c++) m = fmaxf(m, zz[c]);
    float s = 0.f;
#pragma unroll
    for (int c = 0; c < NCLS; c++) s += expf(zz[c] - m);
    float ls = m + logf(s);
    float* op = out + NUM_GRAPHS * NCLS + (size_t)n * NCLS;
#pragma unroll
    for (int c = 0; c < NCLS; c++) op[c] = zz[c] - ls;
}

__global__ void decode_g_kernel(float* __restrict__ out) {
    int j = threadIdx.x;
    if (j < NUM_GRAPHS * NCLS) out[j] = funkey(g_gkey[j]);
}

// ---------------------------------------------------------------------------

extern "C" void kernel_launch(void* const* d_in, const int* in_sizes, int n_in,
                              void* d_out, int out_size) {
    const float* x     = (const float*)d_in[0];
    const int*   ei    = (const int*)d_in[1];
    const int*   batch = (const int*)d_in[2];
    const float* W1    = (const float*)d_in[3];
    const float* b1    = (const float*)d_in[4];
    const float* W2    = (const float*)d_in[5];
    const float* b2    = (const float*)d_in[6];
    float* out = (float*)d_out;

    const int N = in_sizes[2];
    const int F = in_sizes[0] / N;
    const int E = in_sizes[1] / 2;

    const int nbN = (N + 255) / 256;
    const int nbE = (E + 255) / 256;

    init_kernel<<<nbN, 256>>>(N);
    deg_kernel<<<nbE, 256>>>(ei, E);
    dinv_kernel<<<nbN, 256>>>(N);

    gemm1_kernel<<<(N + 511) / 512, 256>>>(x, W1, b1, N, F);
    agg1_kernel<<<nbE, 256>>>(ei, E);

    gemm2_kernel<<<nbN, 256>>>(W2, b2, N);
    agg2_kernel<<<nbE, 256>>>(ei, E);

    segmax_logsm_kernel<<<nbN, 256>>>(batch, out, N);
    decode_g_kernel<<<1, 512>>>(out);
}

// round 5
// speedup vs baseline: 2.8061x; 2.8061x over previous
#include <cuda_runtime.h>
#include <cuda_bf16.h>
#include <cstdint>

// ---------------------------------------------------------------------------
// GCN 2-layer: h = relu(GCNConv(x,W1,b1)); z = GCNConv(h,W2,b2)
// out = [ segment_max(z,batch) (64x7) ; log_softmax(z) (Nx7) ]
// edge_index/batch are int32. No tcgen05 (harness PTX targets compute_103,
// which lacks arch-'a' features) -> SIMT fp32 GEMM, software-pipelined.
// ---------------------------------------------------------------------------

#define MAXN 100352
#define NUM_GRAPHS 64
#define HID 16
#define NCLS 7
#define BM 128       // nodes per CTA in gemm1
#define BK 16        // k-chunk

// ---- scratch (device globals; no allocation allowed) ----------------------
__device__ int      g_deg[MAXN];
__device__ float    g_dinv[MAXN];
__device__ float4   g_h0[MAXN * 4];   // [N][16]
__device__ float4   g_a1[MAXN * 4];   // [N][16]
__device__ float4   g_h1[MAXN * 2];   // [N][8]
__device__ float4   g_z [MAXN * 2];   // [N][8]
__device__ unsigned g_gkey[NUM_GRAPHS * NCLS];

// ---- helpers --------------------------------------------------------------

__device__ __forceinline__ void redAdd4(float* p, float a, float b, float c, float d) {
    asm volatile(
        "{ .reg .u64 pg; cvta.to.global.u64 pg, %0;\n\t"
        "  red.global.add.v4.f32 [pg], {%1, %2, %3, %4}; }"
        :: "l"(p), "f"(a), "f"(b), "f"(c), "f"(d) : "memory");
}

__device__ __forceinline__ unsigned fkey(float f) {
    unsigned u = __float_as_uint(f);
    return (u & 0x80000000u) ? ~u : (u | 0x80000000u);
}
__device__ __forceinline__ float funkey(unsigned u) {
    return __uint_as_float((u & 0x80000000u) ? (u ^ 0x80000000u) : ~u);
}

// ---- small pipeline kernels ----------------------------------------------

__global__ void init_kernel(int N) {
    int i = blockIdx.x * blockDim.x + threadIdx.x;
    if (i < N) g_deg[i] = 1;                       // self-loop
    if (i < NUM_GRAPHS * NCLS) g_gkey[i] = 0u;
}

__global__ void deg_kernel(const int* __restrict__ ei, int E) {
    int e = blockIdx.x * blockDim.x + threadIdx.x;
    if (e >= E) return;
    atomicAdd(&g_deg[ei[E + e]], 1);
}

__global__ void dinv_kernel(int N) {
    int i = blockIdx.x * blockDim.x + threadIdx.x;
    if (i < N) g_dinv[i] = rsqrtf((float)g_deg[i]);
}

// ---- GEMM1: h0[N,16] = x[N,F] @ W1[F,16]; a1 = h0*dinv^2 + b1 (fused) -----
// 256 threads, 128-node tile. thread = node (t>>1) x col-half (t&1) -> acc[8].
// Double-buffered smem; LDGs for chunk c+1 are issued before computing c.
__global__ __launch_bounds__(256) void gemm1_kernel(
    const float* __restrict__ x, const float* __restrict__ W1,
    const float* __restrict__ b1, int N, int F)
{
    __shared__ float xs[2][BM * 17];
    __shared__ float ws[2][BK * 16];

    const int t    = threadIdx.x;
    const int r    = t >> 1;          // node row in tile
    const int cg   = t & 1;           // col half
    const int node = blockIdx.x * BM + r;
    const int nch  = (F + BK - 1) / BK;

    const int wkk = t >> 4, wcc = t & 15;   // this thread's W-tile element

    float acc[8];
#pragma unroll
    for (int j = 0; j < 8; j++) acc[j] = 0.f;

    float ld[8];
    float wv;

    // prologue: chunk 0 -> regs -> smem buf 0
    {
        int kb = cg * 8;
#pragma unroll
        for (int j = 0; j < 8; j++) {
            int k = kb + j;
            ld[j] = (node < N && k < F) ? __ldg(&x[(size_t)node * F + k]) : 0.f;
        }
        wv = (wkk < F) ? __ldg(&W1[wkk * 16 + wcc]) : 0.f;
#pragma unroll
        for (int j = 0; j < 8; j++) xs[0][r * 17 + cg * 8 + j] = ld[j];
        ws[0][t] = wv;
    }
    __syncthreads();

    for (int c = 0; c < nch; c++) {
        const int cur = c & 1, nxt = cur ^ 1;
        const bool more = (c + 1 < nch);
        // issue next chunk's loads first (latency hidden by compute below)
        if (more) {
            int k0 = (c + 1) * BK;
            int kb = k0 + cg * 8;
#pragma unroll
            for (int j = 0; j < 8; j++) {
                int k = kb + j;
                ld[j] = (node < N && k < F) ? __ldg(&x[(size_t)node * F + k]) : 0.f;
            }
            int kw = k0 + wkk;
            wv = (kw < F) ? __ldg(&W1[kw * 16 + wcc]) : 0.f;
        }
        // compute chunk c
#pragma unroll
        for (int kk = 0; kk < BK; kk++) {
            float xv = xs[cur][r * 17 + kk];
            float4 w0 = *(const float4*)&ws[cur][kk * 16 + cg * 8];
            float4 w1 = *(const float4*)&ws[cur][kk * 16 + cg * 8 + 4];
            acc[0] += xv * w0.x; acc[1] += xv * w0.y;
            acc[2] += xv * w0.z; acc[3] += xv * w0.w;
            acc[4] += xv * w1.x; acc[5] += xv * w1.y;
            acc[6] += xv * w1.z; acc[7] += xv * w1.w;
        }
        if (more) {
#pragma unroll
            for (int j = 0; j < 8; j++) xs[nxt][r * 17 + cg * 8 + j] = ld[j];
            ws[nxt][t] = wv;
        }
        __syncthreads();
    }

    if (node < N) {
        float di = g_dinv[node];
        float c2 = di * di;
        float* hp = (float*)g_h0 + (size_t)node * 16 + cg * 8;
        float* ap = (float*)g_a1 + (size_t)node * 16 + cg * 8;
        *(float4*)hp       = make_float4(acc[0], acc[1], acc[2], acc[3]);
        *(float4*)(hp + 4) = make_float4(acc[4], acc[5], acc[6], acc[7]);
        *(float4*)ap       = make_float4(acc[0] * c2 + __ldg(&b1[cg * 8 + 0]),
                                         acc[1] * c2 + __ldg(&b1[cg * 8 + 1]),
                                         acc[2] * c2 + __ldg(&b1[cg * 8 + 2]),
                                         acc[3] * c2 + __ldg(&b1[cg * 8 + 3]));
        *(float4*)(ap + 4) = make_float4(acc[4] * c2 + __ldg(&b1[cg * 8 + 4]),
                                         acc[5] * c2 + __ldg(&b1[cg * 8 + 5]),
                                         acc[6] * c2 + __ldg(&b1[cg * 8 + 6]),
                                         acc[7] * c2 + __ldg(&b1[cg * 8 + 7]));
    }
}

// ---- aggregation / layer 2 / epilogue -------------------------------------

__global__ void agg1_kernel(const int* __restrict__ ei, int E) {
    int e = blockIdx.x * blockDim.x + threadIdx.x;
    if (e >= E) return;
    int s = ei[e];
    int d = ei[E + e];
    float coef = g_dinv[s] * g_dinv[d];
    const float4* hp = g_h0 + (size_t)s * 4;
    float* ap = (float*)(g_a1 + (size_t)d * 4);
#pragma unroll
    for (int q = 0; q < 4; q++) {
        float4 v = hp[q];
        redAdd4(ap + q * 4, v.x * coef, v.y * coef, v.z * coef, v.w * coef);
    }
}

__global__ void gemm2_kernel(const float* __restrict__ W2,
                             const float* __restrict__ b2, int N) {
    __shared__ float w2s[HID * NCLS];
    int t = threadIdx.x;
    if (t < HID * NCLS) w2s[t] = W2[t];
    __syncthreads();
    int n = blockIdx.x * blockDim.x + t;
    if (n >= N) return;
    const float4* ap = g_a1 + (size_t)n * 4;
    float r[16];
#pragma unroll
    for (int q = 0; q < 4; q++) {
        float4 v = ap[q];
        r[q * 4 + 0] = fmaxf(v.x, 0.f); r[q * 4 + 1] = fmaxf(v.y, 0.f);
        r[q * 4 + 2] = fmaxf(v.z, 0.f); r[q * 4 + 3] = fmaxf(v.w, 0.f);
    }
    float o[NCLS];
#pragma unroll
    for (int c = 0; c < NCLS; c++) o[c] = 0.f;
#pragma unroll
    for (int j = 0; j < 16; j++) {
        float rv = r[j];
#pragma unroll
        for (int c = 0; c < NCLS; c++) o[c] += rv * w2s[j * NCLS + c];
    }
    float* hp = (float*)(g_h1 + (size_t)n * 2);
    *(float4*)hp       = make_float4(o[0], o[1], o[2], o[3]);
    *(float4*)(hp + 4) = make_float4(o[4], o[5], o[6], 0.f);

    float di = g_dinv[n];
    float c2 = di * di;
    float* zp = (float*)(g_z + (size_t)n * 2);
    *(float4*)zp       = make_float4(o[0] * c2 + __ldg(&b2[0]), o[1] * c2 + __ldg(&b2[1]),
                                     o[2] * c2 + __ldg(&b2[2]), o[3] * c2 + __ldg(&b2[3]));
    *(float4*)(zp + 4) = make_float4(o[4] * c2 + __ldg(&b2[4]), o[5] * c2 + __ldg(&b2[5]),
                                     o[6] * c2 + __ldg(&b2[6]), 0.f);
}

__global__ void agg2_kernel(const int* __restrict__ ei, int E) {
    int e = blockIdx.x * blockDim.x + threadIdx.x;
    if (e >= E) return;
    int s = ei[e];
    int d = ei[E + e];
    float coef = g_dinv[s] * g_dinv[d];
    const float* hp = (const float*)(g_h1 + (size_t)s * 2);
    float* zp = (float*)(g_z + (size_t)d * 2);
    float4 v0 = *(const float4*)hp;
    float4 v1 = *(const float4*)(hp + 4);
    redAdd4(zp,     v0.x * coef, v0.y * coef, v0.z * coef, v0.w * coef);
    redAdd4(zp + 4, v1.x * coef, v1.y * coef, v1.z * coef, 0.f);
}

__global__ void segmax_logsm_kernel(const int* __restrict__ batch,
                                    float* __restrict__ out, int N) {
    int n = blockIdx.x * blockDim.x + threadIdx.x;
    if (n >= N) return;
    const float* zp = (const float*)(g_z + (size_t)n * 2);
    float4 z0 = *(const float4*)zp;
    float4 z1 = *(const float4*)(zp + 4);
    float zz[NCLS] = { z0.x, z0.y, z0.z, z0.w, z1.x, z1.y, z1.z };

    int b = batch[n];
#pragma unroll
    for (int c = 0; c < NCLS; c++)
        atomicMax(&g_gkey[b * NCLS + c], fkey(zz[c]));

    float m = zz[0];
#pragma unroll
    for (int c = 1; c < NCLS; c++) m = fmaxf(m, zz[c]);
    float s = 0.f;
#pragma unroll
    for (int c = 0; c < NCLS; c++) s += expf(zz[c] - m);
    float ls = m + logf(s);
    float* op = out + NUM_GRAPHS * NCLS + (size_t)n * NCLS;
#pragma unroll
    for (int c = 0; c < NCLS; c++) op[c] = zz[c] - ls;
}

__global__ void decode_g_kernel(float* __restrict__ out) {
    int j = threadIdx.x;
    if (j < NUM_GRAPHS * NCLS) out[j] = funkey(g_gkey[j]);
}

// ---------------------------------------------------------------------------

extern "C" void kernel_launch(void* const* d_in, const int* in_sizes, int n_in,
                              void* d_out, int out_size) {
    const float* x     = (const float*)d_in[0];
    const int*   ei    = (const int*)d_in[1];
    const int*   batch = (const int*)d_in[2];
    const float* W1    = (const float*)d_in[3];
    const float* b1    = (const float*)d_in[4];
    const float* W2    = (const float*)d_in[5];
    const float* b2    = (const float*)d_in[6];
    float* out = (float*)d_out;

    const int N = in_sizes[2];
    const int F = in_sizes[0] / N;
    const int E = in_sizes[1] / 2;

    const int nbN = (N + 255) / 256;
    const int nbE = (E + 255) / 256;

    init_kernel<<<nbN, 256>>>(N);
    deg_kernel<<<nbE, 256>>>(ei, E);
    dinv_kernel<<<nbN, 256>>>(N);

    gemm1_kernel<<<(N + BM - 1) / BM, 256>>>(x, W1, b1, N, F);
    agg1_kernel<<<nbE, 256>>>(ei, E);

    gemm2_kernel<<<nbN, 256>>>(W2, b2, N);
    agg2_kernel<<<nbE, 256>>>(ei, E);

    segmax_logsm_kernel<<<nbN, 256>>>(batch, out, N);
    decode_g_kernel<<<1, 512>>>(out);
}

// round 6
// speedup vs baseline: 2.8306x; 1.0087x over previous
#include <cuda_runtime.h>
#include <cuda_bf16.h>
#include <cstdint>

// ---------------------------------------------------------------------------
// GCN 2-layer: h = relu(GCNConv(x,W1,b1)); z = GCNConv(h,W2,b2)
// out = [ segment_max(z,batch) (64x7) ; log_softmax(z) (Nx7) ]
// edge_index/batch are int32. No tcgen05 (compute_103 PTX target).
// GEMM1: coalesced staged loads + software pipeline + packed fma.rn.f32x2.
// ---------------------------------------------------------------------------

#define MAXN 100352
#define NUM_GRAPHS 64
#define HID 16
#define NCLS 7
#define BM 256       // nodes per CTA in gemm1
#define BK 16        // k-chunk

// ---- scratch (device globals; no allocation allowed) ----------------------
__device__ int      g_deg[MAXN];
__device__ float    g_dinv[MAXN];
__device__ float4   g_h0[MAXN * 4];   // [N][16]
__device__ float4   g_a1[MAXN * 4];   // [N][16]
__device__ float4   g_h1[MAXN * 2];   // [N][8]
__device__ float4   g_z [MAXN * 2];   // [N][8]
__device__ unsigned g_gkey[NUM_GRAPHS * NCLS];

// ---- helpers --------------------------------------------------------------

__device__ __forceinline__ void redAdd4(float* p, float a, float b, float c, float d) {
    asm volatile(
        "{ .reg .u64 pg; cvta.to.global.u64 pg, %0;\n\t"
        "  red.global.add.v4.f32 [pg], {%1, %2, %3, %4}; }"
        :: "l"(p), "f"(a), "f"(b), "f"(c), "f"(d) : "memory");
}

__device__ __forceinline__ unsigned fkey(float f) {
    unsigned u = __float_as_uint(f);
    return (u & 0x80000000u) ? ~u : (u | 0x80000000u);
}
__device__ __forceinline__ float funkey(unsigned u) {
    return __uint_as_float((u & 0x80000000u) ? (u ^ 0x80000000u) : ~u);
}

// packed fp32x2 helpers (Blackwell PTX; FFMA2 only reachable via fma.rn.f32x2)
__device__ __forceinline__ void fma2(unsigned long long& d,
                                     unsigned long long a, unsigned long long b) {
    asm("fma.rn.f32x2 %0, %1, %2, %3;" : "=l"(d) : "l"(a), "l"(b), "l"(d));
}
__device__ __forceinline__ unsigned long long bcast2(float v) {
    unsigned long long r;
    asm("mov.b64 %0, {%1, %1};" : "=l"(r) : "f"(v));
    return r;
}
__device__ __forceinline__ float2 unpack2(unsigned long long v) {
    float lo, hi;
    asm("mov.b64 {%0, %1}, %2;" : "=f"(lo), "=f"(hi) : "l"(v));
    return make_float2(lo, hi);
}

// ---- small pipeline kernels ----------------------------------------------

__global__ void init_kernel(int N) {
    int i = blockIdx.x * blockDim.x + threadIdx.x;
    if (i < N) g_deg[i] = 1;                       // self-loop
    if (i < NUM_GRAPHS * NCLS) g_gkey[i] = 0u;
}

__global__ void deg_kernel(const int* __restrict__ ei, int E) {
    int e = blockIdx.x * blockDim.x + threadIdx.x;
    if (e >= E) return;
    atomicAdd(&g_deg[ei[E + e]], 1);
}

__global__ void dinv_kernel(int N) {
    int i = blockIdx.x * blockDim.x + threadIdx.x;
    if (i < N) g_dinv[i] = rsqrtf((float)g_deg[i]);
}

// ---- GEMM1: h0[N,16] = x[N,F] @ W1[F,16]; a1 = h0*dinv^2 + b1 (fused) -----
// 256 threads, 256-node tile. thread = nodes {r, r+128} x col-half cg -> 2x8.
// Coalesced staged loads (half-warp per row), double-buffered, f32x2 FMA.
__global__ __launch_bounds__(256) void gemm1_kernel(
    const float* __restrict__ x, const float* __restrict__ W1,
    const float* __restrict__ b1, int N, int F)
{
    __shared__ float xs[2][BM * 17];
    __shared__ float ws[2][BK * 16];

    const int t  = threadIdx.x;
    const int r  = t >> 1;            // 0..127
    const int cg = t & 1;             // col half
    const int n0 = blockIdx.x * BM;
    const int nch = (F + BK - 1) / BK;

    const int wkk = t >> 4, wcc = t & 15;   // W-tile element owned by thread

    unsigned long long acc0[4], acc1[4];
#pragma unroll
    for (int j = 0; j < 4; j++) { acc0[j] = 0ull; acc1[j] = 0ull; }

    float ld[16];
    float wv;

    // prologue: coalesced load of chunk 0 -> regs -> buf 0
    {
#pragma unroll
        for (int i = 0; i < 16; i++) {
            int idx = t + 256 * i;
            int row = idx >> 4, kl = idx & 15;
            int node = n0 + row;
            ld[i] = (node < N && kl < F) ? __ldg(&x[(size_t)node * F + kl]) : 0.f;
        }
        wv = (wkk < F) ? __ldg(&W1[wkk * 16 + wcc]) : 0.f;
#pragma unroll
        for (int i = 0; i < 16; i++) {
            int idx = t + 256 * i;
            xs[0][(idx >> 4) * 17 + (idx & 15)] = ld[i];
        }
        ws[0][t] = wv;
    }
    __syncthreads();

    for (int c = 0; c < nch; c++) {
        const int cur = c & 1, nxt = cur ^ 1;
        const bool more = (c + 1 < nch);
        // issue next chunk's LDGs first (hidden behind the FMA phase)
        if (more) {
            int k0 = (c + 1) * BK;
#pragma unroll
            for (int i = 0; i < 16; i++) {
                int idx = t + 256 * i;
                int row = idx >> 4, kl = idx & 15;
                int node = n0 + row, k = k0 + kl;
                ld[i] = (node < N && k < F) ? __ldg(&x[(size_t)node * F + k]) : 0.f;
            }
            int kw = k0 + wkk;
            wv = (kw < F) ? __ldg(&W1[kw * 16 + wcc]) : 0.f;
        }
        // compute chunk c: 2 nodes x 8 cols, packed f32x2
#pragma unroll
        for (int kk = 0; kk < BK; kk++) {
            ulonglong2 wA = *(const ulonglong2*)&ws[cur][kk * 16 + cg * 8];
            ulonglong2 wB = *(const ulonglong2*)&ws[cur][kk * 16 + cg * 8 + 4];
            unsigned long long x0 = bcast2(xs[cur][r * 17 + kk]);
            unsigned long long x1 = bcast2(xs[cur][(r + 128) * 17 + kk]);
            fma2(acc0[0], x0, wA.x); fma2(acc0[1], x0, wA.y);
            fma2(acc0[2], x0, wB.x); fma2(acc0[3], x0, wB.y);
            fma2(acc1[0], x1, wA.x); fma2(acc1[1], x1, wA.y);
            fma2(acc1[2], x1, wB.x); fma2(acc1[3], x1, wB.y);
        }
        if (more) {
#pragma unroll
            for (int i = 0; i < 16; i++) {
                int idx = t + 256 * i;
                xs[nxt][(idx >> 4) * 17 + (idx & 15)] = ld[i];
            }
            ws[nxt][t] = wv;
        }
        __syncthreads();
    }

    // epilogue: unpack, write h0 and a1 for both nodes
#pragma unroll
    for (int p = 0; p < 2; p++) {
        int node = n0 + r + 128 * p;
        if (node >= N) continue;
        unsigned long long* acc = p ? acc1 : acc0;
        float2 v0 = unpack2(acc[0]), v1 = unpack2(acc[1]);
        float2 v2 = unpack2(acc[2]), v3 = unpack2(acc[3]);
        float di = g_dinv[node];
        float c2 = di * di;
        float* hp = (float*)g_h0 + (size_t)node * 16 + cg * 8;
        float* ap = (float*)g_a1 + (size_t)node * 16 + cg * 8;
        *(float4*)hp       = make_float4(v0.x, v0.y, v1.x, v1.y);
        *(float4*)(hp + 4) = make_float4(v2.x, v2.y, v3.x, v3.y);
        *(float4*)ap       = make_float4(v0.x * c2 + __ldg(&b1[cg * 8 + 0]),
                                         v0.y * c2 + __ldg(&b1[cg * 8 + 1]),
                                         v1.x * c2 + __ldg(&b1[cg * 8 + 2]),
                                         v1.y * c2 + __ldg(&b1[cg * 8 + 3]));
        *(float4*)(ap + 4) = make_float4(v2.x * c2 + __ldg(&b1[cg * 8 + 4]),
                                         v2.y * c2 + __ldg(&b1[cg * 8 + 5]),
                                         v3.x * c2 + __ldg(&b1[cg * 8 + 6]),
                                         v3.y * c2 + __ldg(&b1[cg * 8 + 7]));
    }
}

// ---- aggregation / layer 2 / epilogue -------------------------------------

__global__ void agg1_kernel(const int* __restrict__ ei, int E) {
    int e = blockIdx.x * blockDim.x + threadIdx.x;
    if (e >= E) return;
    int s = ei[e];
    int d = ei[E + e];
    float coef = g_dinv[s] * g_dinv[d];
    const float4* hp = g_h0 + (size_t)s * 4;
    float* ap = (float*)(g_a1 + (size_t)d * 4);
#pragma unroll
    for (int q = 0; q < 4; q++) {
        float4 v = hp[q];
        redAdd4(ap + q * 4, v.x * coef, v.y * coef, v.z * coef, v.w * coef);
    }
}

__global__ void gemm2_kernel(const float* __restrict__ W2,
                             const float* __restrict__ b2, int N) {
    __shared__ float w2s[HID * NCLS];
    int t = threadIdx.x;
    if (t < HID * NCLS) w2s[t] = W2[t];
    __syncthreads();
    int n = blockIdx.x * blockDim.x + t;
    if (n >= N) return;
    const float4* ap = g_a1 + (size_t)n * 4;
    float r[16];
#pragma unroll
    for (int q = 0; q < 4; q++) {
        float4 v = ap[q];
        r[q * 4 + 0] = fmaxf(v.x, 0.f); r[q * 4 + 1] = fmaxf(v.y, 0.f);
        r[q * 4 + 2] = fmaxf(v.z, 0.f); r[q * 4 + 3] = fmaxf(v.w, 0.f);
    }
    float o[NCLS];
#pragma unroll
    for (int c = 0; c < NCLS; c++) o[c] = 0.f;
#pragma unroll
    for (int j = 0; j < 16; j++) {
        float rv = r[j];
#pragma unroll
        for (int c = 0; c < NCLS; c++) o[c] += rv * w2s[j * NCLS + c];
    }
    float* hp = (float*)(g_h1 + (size_t)n * 2);
    *(float4*)hp       = make_float4(o[0], o[1], o[2], o[3]);
    *(float4*)(hp + 4) = make_float4(o[4], o[5], o[6], 0.f);

    float di = g_dinv[n];
    float c2 = di * di;
    float* zp = (float*)(g_z + (size_t)n * 2);
    *(float4*)zp       = make_float4(o[0] * c2 + __ldg(&b2[0]), o[1] * c2 + __ldg(&b2[1]),
                                     o[2] * c2 + __ldg(&b2[2]), o[3] * c2 + __ldg(&b2[3]));
    *(float4*)(zp + 4) = make_float4(o[4] * c2 + __ldg(&b2[4]), o[5] * c2 + __ldg(&b2[5]),
                                     o[6] * c2 + __ldg(&b2[6]), 0.f);
}

__global__ void agg2_kernel(const int* __restrict__ ei, int E) {
    int e = blockIdx.x * blockDim.x + threadIdx.x;
    if (e >= E) return;
    int s = ei[e];
    int d = ei[E + e];
    float coef = g_dinv[s] * g_dinv[d];
    const float* hp = (const float*)(g_h1 + (size_t)s * 2);
    float* zp = (float*)(g_z + (size_t)d * 2);
    float4 v0 = *(const float4*)hp;
    float4 v1 = *(const float4*)(hp + 4);
    redAdd4(zp,     v0.x * coef, v0.y * coef, v0.z * coef, v0.w * coef);
    redAdd4(zp + 4, v1.x * coef, v1.y * coef, v1.z * coef, 0.f);
}

__global__ void segmax_logsm_kernel(const int* __restrict__ batch,
                                    float* __restrict__ out, int N) {
    int n = blockIdx.x * blockDim.x + threadIdx.x;
    if (n >= N) return;
    const float* zp = (const float*)(g_z + (size_t)n * 2);
    float4 z0 = *(const float4*)zp;
    float4 z1 = *(const float4*)(zp + 4);
    float zz[NCLS] = { z0.x, z0.y, z0.z, z0.w, z1.x, z1.y, z1.z };

    int b = batch[n];
#pragma unroll
    for (int c = 0; c < NCLS; c++)
        atomicMax(&g_gkey[b * NCLS + c], fkey(zz[c]));

    float m = zz[0];
#pragma unroll
    for (int c = 1; c < NCLS; c++) m = fmaxf(m, zz[c]);
    float s = 0.f;
#pragma unroll
    for (int c = 0; c < NCLS; c++) s += expf(zz[c] - m);
    float ls = m + logf(s);
    float* op = out + NUM_GRAPHS * NCLS + (size_t)n * NCLS;
#pragma unroll
    for (int c = 0; c < NCLS; c++) op[c] = zz[c] - ls;
}

__global__ void decode_g_kernel(float* __restrict__ out) {
    int j = threadIdx.x;
    if (j < NUM_GRAPHS * NCLS) out[j] = funkey(g_gkey[j]);
}

// ---------------------------------------------------------------------------

extern "C" void kernel_launch(void* const* d_in, const int* in_sizes, int n_in,
                              void* d_out, int out_size) {
    const float* x     = (const float*)d_in[0];
    const int*   ei    = (const int*)d_in[1];
    const int*   batch = (const int*)d_in[2];
    const float* W1    = (const float*)d_in[3];
    const float* b1    = (const float*)d_in[4];
    const float* W2    = (const float*)d_in[5];
    const float* b2    = (const float*)d_in[6];
    float* out = (float*)d_out;

    const int N = in_sizes[2];
    const int F = in_sizes[0] / N;
    const int E = in_sizes[1] / 2;

    const int nbN = (N + 255) / 256;
    const int nbE = (E + 255) / 256;

    init_kernel<<<nbN, 256>>>(N);
    deg_kernel<<<nbE, 256>>>(ei, E);
    dinv_kernel<<<nbN, 256>>>(N);

    gemm1_kernel<<<(N + BM - 1) / BM, 256>>>(x, W1, b1, N, F);
    agg1_kernel<<<nbE, 256>>>(ei, E);

    gemm2_kernel<<<nbN, 256>>>(W2, b2, N);
    agg2_kernel<<<nbE, 256>>>(ei, E);

    segmax_logsm_kernel<<<nbN, 256>>>(batch, out, N);
    decode_g_kernel<<<1, 512>>>(out);
}